// round 12
// baseline (speedup 1.0000x reference)
#include <cuda_runtime.h>
#include <math.h>

// ---------------- problem constants ------------------------------------------
#define Nn 8000
#define Ee 128000
#define Ff 128
#define Zz 10
#define NF (Nn*Ff)

#define NBLK_UP 1010            // sum_z ceil(cnt_z/8) <= 1000 + 10
#define LIST_CAP (NBLK_UP*8)    // 8080

// ---------------- normalization constants ------------------------------------
#define INV_SQF   0.08838834764831845f     // 1/sqrt(128)
#define INV_SQFZ  0.027950849718747373f    // 1/(sqrt(128)*sqrt(10))
#define SQ3c      1.7320508075688772f
#define INV_SQ3   0.5773502691896258f
#define INV_SQZ   0.31622776601683794f
#define INV_SQ8   0.35355339059327373f     // 1/sqrt(8)
#define TP_SCALE  0.03125f                 // EPS(0.25) * (1/8 mix fan-in)

// ---------------- scratch (static device globals; no allocation) -------------
__device__ float g_x0[NF];        // linear_up scalars     [N][F]
__device__ float g_x1[3*NF];      // linear_up vectors SoA [3][N][F]
__device__ float g_sc0[NF];       // skip scalars          [N][F]
__device__ float g_sc1[3*NF];     // skip vectors SoA      [3][N][F]
__device__ float g_h3[Ee*64];     // radial MLP hidden     [E][64] (original edge order)
__device__ float g_a0[NF];        // scatter accum scalars [N][F]
__device__ float g_a1[3*NF];      // scatter accum vec SoA [3][N][F]

// species grouping (for k_up_g)
__device__ int g_cnt[Zz];
__device__ int g_cur[Zz];
__device__ int g_off[Zz + 1];     // block-offset prefix (in 8-node blocks)
__device__ int g_list[LIST_CAP];

// receiver-sorted edge order (for k_mixtp scatter merging)
__device__ int g_rcnt[Nn];
__device__ int g_rcur[Nn];
__device__ int g_eord[Ee];

__device__ __forceinline__ float silu_f(float x) { return x / (1.0f + expf(-x)); }

__device__ __forceinline__ void red4(float* p, float a, float b, float c, float d) {
    asm volatile("red.global.add.v4.f32 [%0], {%1,%2,%3,%4};"
                 :: "l"(p), "f"(a), "f"(b), "f"(c), "f"(d) : "memory");
}

// ---------------- zero accumulators + grouping state --------------------------
__global__ void k_zero() {
    int stride = gridDim.x * blockDim.x;
    int tid = blockIdx.x * blockDim.x + threadIdx.x;
    float4 z4 = make_float4(0.f, 0.f, 0.f, 0.f);
    float4* a0 = reinterpret_cast<float4*>(g_a0);
    float4* a1 = reinterpret_cast<float4*>(g_a1);
    for (int i = tid; i < NF/4; i += stride) a0[i] = z4;
    for (int i = tid; i < 3*NF/4; i += stride) a1[i] = z4;
    for (int i = tid; i < LIST_CAP; i += stride) g_list[i] = -1;
    for (int i = tid; i < Nn; i += stride) g_rcnt[i] = 0;
    if (tid < Zz) g_cnt[tid] = 0;
}

// ---------------- species grouping: count / scan / scatter --------------------
__global__ void k_count(const int* __restrict__ species) {
    int n = blockIdx.x * blockDim.x + threadIdx.x;
    if (n < Nn) atomicAdd(&g_cnt[species[n]], 1);
}

__global__ void k_scan() {
    if (threadIdx.x == 0 && blockIdx.x == 0) {
        int off = 0;                       // in units of 8-node blocks
        for (int z = 0; z < Zz; z++) {
            g_off[z] = off;
            g_cur[z] = off * 8;
            off += (g_cnt[z] + 7) >> 3;
        }
        g_off[Zz] = off;
    }
}

__global__ void k_scatter(const int* __restrict__ species) {
    int n = blockIdx.x * blockDim.x + threadIdx.x;
    if (n < Nn) {
        int pos = atomicAdd(&g_cur[species[n]], 1);
        g_list[pos] = n;
    }
}

// ---------------- receiver counting sort: count / scan / scatter --------------
__global__ void k_countR(const int* __restrict__ receivers) {
    int e = blockIdx.x * blockDim.x + threadIdx.x;
    if (e < Ee) atomicAdd(&g_rcnt[receivers[e]], 1);
}

// single block, 256 threads, 32 bins/thread (8192 >= 8000)
__global__ __launch_bounds__(256) void k_scanR() {
    __shared__ int part[256];
    int t = threadIdx.x;
    int base = t * 32;
    int sum = 0;
    for (int i = 0; i < 32; i++) {
        int b = base + i;
        if (b < Nn) sum += g_rcnt[b];
    }
    part[t] = sum;
    __syncthreads();
    for (int off = 1; off < 256; off <<= 1) {
        int v = (t >= off) ? part[t - off] : 0;
        __syncthreads();
        part[t] += v;
        __syncthreads();
    }
    int run = part[t] - sum;   // exclusive prefix of this thread's chunk
    for (int i = 0; i < 32; i++) {
        int b = base + i;
        if (b < Nn) { g_rcur[b] = run; run += g_rcnt[b]; }
    }
}

__global__ void k_scatR(const int* __restrict__ receivers) {
    int e = blockIdx.x * blockDim.x + threadIdx.x;
    if (e < Ee) {
        int pos = atomicAdd(&g_rcur[receivers[e]], 1);
        g_eord[pos] = e;
    }
}

// ---------------- linear_up + species skip, 8 same-species nodes per block ----
__global__ __launch_bounds__(128) void k_up_g(
    const float* __restrict__ nf0, const float* __restrict__ nf1,
    const float* __restrict__ wu0, const float* __restrict__ wu1,
    const float* __restrict__ wz0a, const float* __restrict__ wz1a)
{
    int b = blockIdx.x;
    if (b >= g_off[Zz]) return;
    int z = 0;
    #pragma unroll
    for (int t = 1; t <= Zz; t++) if (b >= g_off[t]) z = t;
    int g = threadIdx.x;
    __shared__ int nd[8];
    __shared__ float s0t[128][8], sxt[128][8], syt[128][8], szt[128][8];
    if (g < 8) nd[g] = g_list[b*8 + g];
    __syncthreads();
    #pragma unroll
    for (int i = 0; i < 8; i++) {
        int ni = nd[i];
        float a = 0.f, bx = 0.f, by = 0.f, bz = 0.f;
        if (ni >= 0) {
            a = nf0[ni*Ff + g];
            const float* p = &nf1[(ni*Ff + g)*3];
            bx = p[0]; by = p[1]; bz = p[2];
        }
        s0t[g][i] = a; sxt[g][i] = bx; syt[g][i] = by; szt[g][i] = bz;
    }
    __syncthreads();

    const float* wz0 = wz0a + z*16384;
    const float* wz1 = wz1a + z*16384;

    float x0[8] = {}, xx[8] = {}, xy[8] = {}, xz[8] = {};
    float c0[8] = {}, cx[8] = {}, cy[8] = {}, cz[8] = {};
    #pragma unroll 4
    for (int f = 0; f < 128; f++) {
        float u0 = wu0[f*128 + g];
        float u1 = wu1[f*128 + g];
        float z0 = wz0[f*128 + g];
        float z1 = wz1[f*128 + g];
        float av[8], bxv[8], byv[8], bzv[8];
        *reinterpret_cast<float4*>(&av[0])  = *reinterpret_cast<const float4*>(&s0t[f][0]);
        *reinterpret_cast<float4*>(&av[4])  = *reinterpret_cast<const float4*>(&s0t[f][4]);
        *reinterpret_cast<float4*>(&bxv[0]) = *reinterpret_cast<const float4*>(&sxt[f][0]);
        *reinterpret_cast<float4*>(&bxv[4]) = *reinterpret_cast<const float4*>(&sxt[f][4]);
        *reinterpret_cast<float4*>(&byv[0]) = *reinterpret_cast<const float4*>(&syt[f][0]);
        *reinterpret_cast<float4*>(&byv[4]) = *reinterpret_cast<const float4*>(&syt[f][4]);
        *reinterpret_cast<float4*>(&bzv[0]) = *reinterpret_cast<const float4*>(&szt[f][0]);
        *reinterpret_cast<float4*>(&bzv[4]) = *reinterpret_cast<const float4*>(&szt[f][4]);
        #pragma unroll
        for (int i = 0; i < 8; i++) {
            x0[i] += av[i]*u0;   c0[i] += av[i]*z0;
            xx[i] += bxv[i]*u1;  xy[i] += byv[i]*u1;  xz[i] += bzv[i]*u1;
            cx[i] += bxv[i]*z1;  cy[i] += byv[i]*z1;  cz[i] += bzv[i]*z1;
        }
    }
    #pragma unroll
    for (int i = 0; i < 8; i++) {
        int ni = nd[i];
        if (ni < 0) continue;
        int o = ni*Ff + g;
        g_x0[o]        = x0[i]*INV_SQF;
        g_x1[o]        = xx[i]*INV_SQF;
        g_x1[NF + o]   = xy[i]*INV_SQF;
        g_x1[2*NF + o] = xz[i]*INV_SQF;
        g_sc0[o]        = c0[i]*INV_SQFZ;
        g_sc1[o]        = cx[i]*INV_SQFZ;
        g_sc1[NF + o]   = cy[i]*INV_SQFZ;
        g_sc1[2*NF + o] = cz[i]*INV_SQFZ;
    }
}

// ---------------- radial MLP layers 1..3 (fused, thread-per-edge) -------------
__global__ __launch_bounds__(128) void k_mlp(
    const float* __restrict__ radial,
    const float* __restrict__ w1, const float* __restrict__ w2,
    const float* __restrict__ w3)
{
    __shared__ float sw1[64*8];    // transposed [j][k]
    __shared__ float sw2[64*64];
    __shared__ float sw3[64*64];
    int tid = threadIdx.x;
    for (int i = tid; i < 512; i += 128)
        sw1[i] = w1[(i & 7)*64 + (i >> 3)];
    for (int i = tid; i < 4096; i += 128) {
        sw2[i] = w2[(i & 63)*64 + (i >> 6)];
        sw3[i] = w3[(i & 63)*64 + (i >> 6)];
    }
    __syncthreads();

    int e = blockIdx.x*128 + tid;
    float4 r0 = *reinterpret_cast<const float4*>(&radial[e*8]);
    float4 r1 = *reinterpret_cast<const float4*>(&radial[e*8 + 4]);

    float h[64];
    #pragma unroll
    for (int j = 0; j < 64; j++) {
        const float4* wp = reinterpret_cast<const float4*>(&sw1[j*8]);
        float4 wa = wp[0], wb = wp[1];
        float acc = r0.x*wa.x + r0.y*wa.y + r0.z*wa.z + r0.w*wa.w
                  + r1.x*wb.x + r1.y*wb.y + r1.z*wb.z + r1.w*wb.w;
        h[j] = silu_f(acc * INV_SQ8);
    }
    float h2[64];
    #pragma unroll
    for (int j = 0; j < 64; j++) {
        const float4* wp = reinterpret_cast<const float4*>(&sw2[j*64]);
        float a0 = 0.f, a1 = 0.f, a2 = 0.f, a3 = 0.f;
        #pragma unroll
        for (int k = 0; k < 16; k++) {
            float4 w = wp[k];
            a0 += h[4*k+0]*w.x; a1 += h[4*k+1]*w.y;
            a2 += h[4*k+2]*w.z; a3 += h[4*k+3]*w.w;
        }
        h2[j] = silu_f((a0+a1+a2+a3) * 0.125f);
    }
    #pragma unroll
    for (int j = 0; j < 64; j++) {
        const float4* wp = reinterpret_cast<const float4*>(&sw3[j*64]);
        float a0 = 0.f, a1 = 0.f, a2 = 0.f, a3 = 0.f;
        #pragma unroll
        for (int k = 0; k < 16; k++) {
            float4 w = wp[k];
            a0 += h2[4*k+0]*w.x; a1 += h2[4*k+1]*w.y;
            a2 += h2[4*k+2]*w.z; a3 += h2[4*k+3]*w.w;
        }
        h[j] = silu_f((a0+a1+a2+a3) * 0.125f);
    }
    float4* dst = reinterpret_cast<float4*>(&g_h3[e*64]);
    #pragma unroll
    for (int j = 0; j < 16; j++)
        dst[j] = make_float4(h[4*j], h[4*j+1], h[4*j+2], h[4*j+3]);
}

// ---------------- fused mix-GEMM + tensor product + scatter -------------------
// block = 32 receiver-sorted edges (via g_eord), 256 threads, 2 blocks/SM.
// Each thread owns 2 consecutive sorted edges; when they share a receiver
// (prob ~15/16 at avg degree 16) their TP outputs merge into one red4 set.
__global__ __launch_bounds__(256, 2) void k_mixtp(
    const float* __restrict__ vectors,
    const int*   __restrict__ senders,
    const int*   __restrict__ receivers,
    const float* __restrict__ w4)
{
    __shared__ float sh_h[32][64];     //  8192 B
    __shared__ float sh_w[8][640];     // 20480 B
    __shared__ float sh_Y[32][3];
    __shared__ int   sh_s[32], sh_r[32], sh_e[32];

    int tid = threadIdx.x;
    int p0  = blockIdx.x * 32;

    // per-edge data (sorted order)
    if (tid < 32) {
        int e = g_eord[p0 + tid];
        sh_e[tid] = e;
        sh_s[tid] = senders[e];
        sh_r[tid] = receivers[e];
        float vx = vectors[e*3+0], vy = vectors[e*3+1], vz = vectors[e*3+2];
        float inv = SQ3c / (sqrtf(vx*vx + vy*vy + vz*vz) + 1e-12f);
        sh_Y[tid][0] = vx*inv; sh_Y[tid][1] = vy*inv; sh_Y[tid][2] = vz*inv;
    }
    __syncthreads();
    // h tile [32][64] gathered through edge order (256B contiguous per row)
    for (int i = tid; i < 512; i += 256) {
        int row = i >> 4, c = i & 15;
        *reinterpret_cast<float4*>(&sh_h[row][c*4]) =
            *reinterpret_cast<const float4*>(&g_h3[sh_e[row]*64 + c*4]);
    }

    int er  = (tid >> 4) * 2;        // local edge rows er, er+1
    int q   = tid & 15;
    int cg0 = q * 4;                 // feature group 0: [cg0, cg0+4)
    int cg1 = 64 + q * 4;            // feature group 1

    float acc[5][2][8] = {};

    for (int kb = 0; kb < 64; kb += 8) {
        __syncthreads();
        // stage w4 chunk [8][640]
        for (int i = tid; i < 1280; i += 256) {
            int row = i / 160, c = i % 160;
            *reinterpret_cast<float4*>(&sh_w[row][c*4]) =
                *reinterpret_cast<const float4*>(&w4[(kb+row)*640 + c*4]);
        }
        __syncthreads();
        #pragma unroll
        for (int k = 0; k < 8; k++) {
            float a0 = sh_h[er][kb+k];
            float a1 = sh_h[er+1][kb+k];
            #pragma unroll
            for (int p = 0; p < 5; p++) {
                float4 b0 = *reinterpret_cast<const float4*>(&sh_w[k][p*128 + cg0]);
                float4 b1 = *reinterpret_cast<const float4*>(&sh_w[k][p*128 + cg1]);
                acc[p][0][0] += a0*b0.x; acc[p][0][1] += a0*b0.y;
                acc[p][0][2] += a0*b0.z; acc[p][0][3] += a0*b0.w;
                acc[p][0][4] += a0*b1.x; acc[p][0][5] += a0*b1.y;
                acc[p][0][6] += a0*b1.z; acc[p][0][7] += a0*b1.w;
                acc[p][1][0] += a1*b0.x; acc[p][1][1] += a1*b0.y;
                acc[p][1][2] += a1*b0.z; acc[p][1][3] += a1*b0.w;
                acc[p][1][4] += a1*b1.x; acc[p][1][5] += a1*b1.y;
                acc[p][1][6] += a1*b1.z; acc[p][1][7] += a1*b1.w;
            }
        }
    }

    // epilogue: tensor product per edge; merge REDs when receivers match
    int s0v = sh_s[er],   r0v = sh_r[er];
    int s1v = sh_s[er+1], r1v = sh_r[er+1];
    float Y0x = sh_Y[er][0],   Y0y = sh_Y[er][1],   Y0z = sh_Y[er][2];
    float Y1x = sh_Y[er+1][0], Y1y = sh_Y[er+1][1], Y1z = sh_Y[er+1][2];

    #pragma unroll
    for (int grp = 0; grp < 2; grp++) {
        int cg = grp ? cg1 : cg0;
        float oA0[4], oAx[4], oAy[4], oAz[4];   // edge er
        float oB0[4], oBx[4], oBy[4], oBz[4];   // edge er+1
        // edge er
        {
            float m0a[4], mxa[4], mya[4], mza[4];
            *reinterpret_cast<float4*>(m0a) = *reinterpret_cast<const float4*>(&g_x0[s0v*Ff + cg]);
            *reinterpret_cast<float4*>(mxa) = *reinterpret_cast<const float4*>(&g_x1[s0v*Ff + cg]);
            *reinterpret_cast<float4*>(mya) = *reinterpret_cast<const float4*>(&g_x1[NF + s0v*Ff + cg]);
            *reinterpret_cast<float4*>(mza) = *reinterpret_cast<const float4*>(&g_x1[2*NF + s0v*Ff + cg]);
            #pragma unroll
            for (int j = 0; j < 4; j++) {
                int jj = grp*4 + j;
                float w0 = acc[0][0][jj], w1 = acc[1][0][jj];
                float w2 = acc[2][0][jj], w3 = acc[3][0][jj], w4c = acc[4][0][jj];
                float M0 = m0a[j], M1x = mxa[j], M1y = mya[j], M1z = mza[j];
                float dot = (M1x*Y0x + M1y*Y0y + M1z*Y0z) * INV_SQ3;
                oA0[j] = (w0*M0 + w1*dot) * TP_SCALE;
                float oux = M0*Y0x*INV_SQ3, ouy = M0*Y0y*INV_SQ3, ouz = M0*Y0z*INV_SQ3;
                float crx = (M1y*Y0z - M1z*Y0y) * INV_SQ3;
                float cry = (M1z*Y0x - M1x*Y0z) * INV_SQ3;
                float crz = (M1x*Y0y - M1y*Y0x) * INV_SQ3;
                oAx[j] = (w2*oux + w3*M1x + w4c*crx) * TP_SCALE;
                oAy[j] = (w2*ouy + w3*M1y + w4c*cry) * TP_SCALE;
                oAz[j] = (w2*ouz + w3*M1z + w4c*crz) * TP_SCALE;
            }
        }
        // edge er+1
        {
            float m0a[4], mxa[4], mya[4], mza[4];
            *reinterpret_cast<float4*>(m0a) = *reinterpret_cast<const float4*>(&g_x0[s1v*Ff + cg]);
            *reinterpret_cast<float4*>(mxa) = *reinterpret_cast<const float4*>(&g_x1[s1v*Ff + cg]);
            *reinterpret_cast<float4*>(mya) = *reinterpret_cast<const float4*>(&g_x1[NF + s1v*Ff + cg]);
            *reinterpret_cast<float4*>(mza) = *reinterpret_cast<const float4*>(&g_x1[2*NF + s1v*Ff + cg]);
            #pragma unroll
            for (int j = 0; j < 4; j++) {
                int jj = grp*4 + j;
                float w0 = acc[0][1][jj], w1 = acc[1][1][jj];
                float w2 = acc[2][1][jj], w3 = acc[3][1][jj], w4c = acc[4][1][jj];
                float M0 = m0a[j], M1x = mxa[j], M1y = mya[j], M1z = mza[j];
                float dot = (M1x*Y1x + M1y*Y1y + M1z*Y1z) * INV_SQ3;
                oB0[j] = (w0*M0 + w1*dot) * TP_SCALE;
                float oux = M0*Y1x*INV_SQ3, ouy = M0*Y1y*INV_SQ3, ouz = M0*Y1z*INV_SQ3;
                float crx = (M1y*Y1z - M1z*Y1y) * INV_SQ3;
                float cry = (M1z*Y1x - M1x*Y1z) * INV_SQ3;
                float crz = (M1x*Y1y - M1y*Y1x) * INV_SQ3;
                oBx[j] = (w2*oux + w3*M1x + w4c*crx) * TP_SCALE;
                oBy[j] = (w2*ouy + w3*M1y + w4c*cry) * TP_SCALE;
                oBz[j] = (w2*ouz + w3*M1z + w4c*crz) * TP_SCALE;
            }
        }
        if (r0v == r1v) {
            red4(&g_a0[r0v*Ff + cg],        oA0[0]+oB0[0], oA0[1]+oB0[1], oA0[2]+oB0[2], oA0[3]+oB0[3]);
            red4(&g_a1[r0v*Ff + cg],        oAx[0]+oBx[0], oAx[1]+oBx[1], oAx[2]+oBx[2], oAx[3]+oBx[3]);
            red4(&g_a1[NF + r0v*Ff + cg],   oAy[0]+oBy[0], oAy[1]+oBy[1], oAy[2]+oBy[2], oAy[3]+oBy[3]);
            red4(&g_a1[2*NF + r0v*Ff + cg], oAz[0]+oBz[0], oAz[1]+oBz[1], oAz[2]+oBz[2], oAz[3]+oBz[3]);
        } else {
            red4(&g_a0[r0v*Ff + cg],        oA0[0], oA0[1], oA0[2], oA0[3]);
            red4(&g_a1[r0v*Ff + cg],        oAx[0], oAx[1], oAx[2], oAx[3]);
            red4(&g_a1[NF + r0v*Ff + cg],   oAy[0], oAy[1], oAy[2], oAy[3]);
            red4(&g_a1[2*NF + r0v*Ff + cg], oAz[0], oAz[1], oAz[2], oAz[3]);
            red4(&g_a0[r1v*Ff + cg],        oB0[0], oB0[1], oB0[2], oB0[3]);
            red4(&g_a1[r1v*Ff + cg],        oBx[0], oBx[1], oBx[2], oBx[3]);
            red4(&g_a1[NF + r1v*Ff + cg],   oBy[0], oBy[1], oBy[2], oBy[3]);
            red4(&g_a1[2*NF + r1v*Ff + cg], oBz[0], oBz[1], oBz[2], oBz[3]);
        }
    }
}

// ---------------- down + symmetric contraction + post + readout ---------------
__global__ __launch_bounds__(128) void k_post_g(
    const int*   __restrict__ species,
    const float* __restrict__ wd0, const float* __restrict__ wd1,
    const float* __restrict__ wsc_all,
    const float* __restrict__ wp0, const float* __restrict__ wp1,
    const float* __restrict__ wr0,
    float* __restrict__ out_node, float* __restrict__ out_f0,
    float* __restrict__ out_f1)
{
    int g = threadIdx.x;
    int nb = blockIdx.x * 8;
    __shared__ float t0[128][8], tx[128][8], ty[128][8], tz[128][8];
    #pragma unroll
    for (int i = 0; i < 8; i++) {
        int o = (nb+i)*Ff + g;
        t0[g][i] = g_a0[o];
        tx[g][i] = g_a1[o];
        ty[g][i] = g_a1[NF + o];
        tz[g][i] = g_a1[2*NF + o];
    }
    __syncthreads();

    float s[8] = {}, v0[8] = {}, v1[8] = {}, v2[8] = {};
    #pragma unroll 4
    for (int f = 0; f < 128; f++) {
        float a = wd0[f*128 + g];
        float b = wd1[f*128 + g];
        float av[8], bxv[8], byv[8], bzv[8];
        *reinterpret_cast<float4*>(&av[0])  = *reinterpret_cast<const float4*>(&t0[f][0]);
        *reinterpret_cast<float4*>(&av[4])  = *reinterpret_cast<const float4*>(&t0[f][4]);
        *reinterpret_cast<float4*>(&bxv[0]) = *reinterpret_cast<const float4*>(&tx[f][0]);
        *reinterpret_cast<float4*>(&bxv[4]) = *reinterpret_cast<const float4*>(&tx[f][4]);
        *reinterpret_cast<float4*>(&byv[0]) = *reinterpret_cast<const float4*>(&ty[f][0]);
        *reinterpret_cast<float4*>(&byv[4]) = *reinterpret_cast<const float4*>(&ty[f][4]);
        *reinterpret_cast<float4*>(&bzv[0]) = *reinterpret_cast<const float4*>(&tz[f][0]);
        *reinterpret_cast<float4*>(&bzv[4]) = *reinterpret_cast<const float4*>(&tz[f][4]);
        #pragma unroll
        for (int i = 0; i < 8; i++) {
            s[i]  += av[i]*a;
            v0[i] += bxv[i]*b; v1[i] += byv[i]*b; v2[i] += bzv[i]*b;
        }
    }

    float b0[8], cc[8];
    #pragma unroll
    for (int i = 0; i < 8; i++) {
        float ss = s[i]*INV_SQF;
        float wx = v0[i]*INV_SQF, wy = v1[i]*INV_SQF, wz = v2[i]*INV_SQF;
        v0[i] = wx; v1[i] = wy; v2[i] = wz;
        float vv = wx*wx + wy*wy + wz*wz;
        float s2 = ss*ss;
        int sp = species[nb+i];
        const float* w = wsc_all + sp*1152;
        b0[i] = (w[g]*ss + w[128+g]*s2 + w[256+g]*vv
               + w[384+g]*s2*ss + w[512+g]*ss*vv) * INV_SQZ;
        cc[i] = (w[640+g] + w[768+g]*ss + w[896+g]*s2
               + w[1024+g]*vv) * INV_SQZ;
    }
    __syncthreads();
    #pragma unroll
    for (int i = 0; i < 8; i++) {
        t0[g][i] = b0[i];
        tx[g][i] = cc[i]*v0[i];
        ty[g][i] = cc[i]*v1[i];
        tz[g][i] = cc[i]*v2[i];
    }
    __syncthreads();

    float f0[8] = {}, f1x[8] = {}, f1y[8] = {}, f1z[8] = {};
    #pragma unroll 4
    for (int f = 0; f < 128; f++) {
        float a = wp0[f*128 + g];
        float b = wp1[f*128 + g];
        float av[8], bxv[8], byv[8], bzv[8];
        *reinterpret_cast<float4*>(&av[0])  = *reinterpret_cast<const float4*>(&t0[f][0]);
        *reinterpret_cast<float4*>(&av[4])  = *reinterpret_cast<const float4*>(&t0[f][4]);
        *reinterpret_cast<float4*>(&bxv[0]) = *reinterpret_cast<const float4*>(&tx[f][0]);
        *reinterpret_cast<float4*>(&bxv[4]) = *reinterpret_cast<const float4*>(&tx[f][4]);
        *reinterpret_cast<float4*>(&byv[0]) = *reinterpret_cast<const float4*>(&ty[f][0]);
        *reinterpret_cast<float4*>(&byv[4]) = *reinterpret_cast<const float4*>(&ty[f][4]);
        *reinterpret_cast<float4*>(&bzv[0]) = *reinterpret_cast<const float4*>(&tz[f][0]);
        *reinterpret_cast<float4*>(&bzv[4]) = *reinterpret_cast<const float4*>(&tz[f][4]);
        #pragma unroll
        for (int i = 0; i < 8; i++) {
            f0[i]  += av[i]*a;
            f1x[i] += bxv[i]*b; f1y[i] += byv[i]*b; f1z[i] += bzv[i]*b;
        }
    }

    float wr = wr0[g];
    float cr[8];
    #pragma unroll
    for (int i = 0; i < 8; i++) {
        int o = (nb+i)*Ff + g;
        float F0 = f0[i]*INV_SQF  + g_sc0[o];
        float X  = f1x[i]*INV_SQF + g_sc1[o];
        float Y  = f1y[i]*INV_SQF + g_sc1[NF + o];
        float Zv = f1z[i]*INV_SQF + g_sc1[2*NF + o];
        out_f0[o] = F0;
        float* po = &out_f1[o*3];
        po[0] = X; po[1] = Y; po[2] = Zv;
        cr[i] = F0 * wr;
    }
    #pragma unroll
    for (int off = 16; off; off >>= 1)
        #pragma unroll
        for (int i = 0; i < 8; i++)
            cr[i] += __shfl_down_sync(0xffffffffu, cr[i], off);
    __shared__ float sred[4][8];
    int lane = g & 31, wrp = g >> 5;
    if (lane == 0)
        #pragma unroll
        for (int i = 0; i < 8; i++) sred[wrp][i] = cr[i];
    __syncthreads();
    if (g < 8)
        out_node[nb+g] = (sred[0][g] + sred[1][g] + sred[2][g] + sred[3][g]) * INV_SQF;
}

// ---------------- launch ------------------------------------------------------
extern "C" void kernel_launch(void* const* d_in, const int* in_sizes, int n_in,
                              void* d_out, int out_size)
{
    const float* vectors   = (const float*)d_in[0];
    const float* nf0       = (const float*)d_in[1];
    const float* nf1       = (const float*)d_in[2];
    const float* radial    = (const float*)d_in[3];
    const int*   species   = (const int*)  d_in[4];
    const int*   senders   = (const int*)  d_in[5];
    const int*   receivers = (const int*)  d_in[6];
    const float* wz0       = (const float*)d_in[7];
    const float* wz1       = (const float*)d_in[8];
    const float* wu0       = (const float*)d_in[9];
    const float* wu1       = (const float*)d_in[10];
    const float* mw1       = (const float*)d_in[11];
    const float* mw2       = (const float*)d_in[12];
    const float* mw3       = (const float*)d_in[13];
    const float* mw4       = (const float*)d_in[14];
    const float* wd0       = (const float*)d_in[15];
    const float* wd1       = (const float*)d_in[16];
    const float* wsc       = (const float*)d_in[17];
    const float* wp0       = (const float*)d_in[18];
    const float* wp1       = (const float*)d_in[19];
    const float* wr0       = (const float*)d_in[20];

    float* out      = (float*)d_out;
    float* out_node = out;                 // [N]
    float* out_f0   = out + Nn;            // [N,F]
    float* out_f1   = out + Nn + NF;       // [N,F,3]

    // k_mlp placed 4th — the slot ncu captured last round — to profile it.
    k_zero   <<<512, 256>>>();
    k_count  <<<(Nn+255)/256, 256>>>(species);
    k_scan   <<<1, 32>>>();
    k_mlp    <<<Ee/128, 128>>>(radial, mw1, mw2, mw3);
    k_scatter<<<(Nn+255)/256, 256>>>(species);
    k_countR <<<Ee/256, 256>>>(receivers);
    k_scanR  <<<1, 256>>>();
    k_scatR  <<<Ee/256, 256>>>(receivers);
    k_up_g   <<<NBLK_UP, 128>>>(nf0, nf1, wu0, wu1, wz0, wz1);
    k_mixtp  <<<Ee/32, 256>>>(vectors, senders, receivers, mw4);
    k_post_g <<<Nn/8, 128>>>(species, wd0, wd1, wsc, wp0, wp1, wr0,
                             out_node, out_f0, out_f1);
}

// round 17
// speedup vs baseline: 1.3060x; 1.3060x over previous
#include <cuda_runtime.h>
#include <math.h>

// ---------------- problem constants ------------------------------------------
#define Nn 8000
#define Ee 128000
#define Ff 128
#define Zz 10
#define NF (Nn*Ff)

#define NBLK_UP 1010            // sum_z ceil(cnt_z/8) <= 1000 + 10
#define LIST_CAP (NBLK_UP*8)    // 8080

// ---------------- normalization constants ------------------------------------
#define INV_SQF   0.08838834764831845f     // 1/sqrt(128)
#define INV_SQFZ  0.027950849718747373f    // 1/(sqrt(128)*sqrt(10))
#define SQ3c      1.7320508075688772f
#define INV_SQ3   0.5773502691896258f
#define INV_SQZ   0.31622776601683794f
#define INV_SQ8   0.35355339059327373f     // 1/sqrt(8)
#define TP_SCALE  0.03125f                 // EPS(0.25) * (1/8 mix fan-in)

// ---------------- scratch (static device globals; no allocation) -------------
__device__ float g_x0[NF];        // linear_up scalars     [N][F]
__device__ float g_x1[3*NF];      // linear_up vectors SoA [3][N][F]
__device__ float g_sc0[NF];       // skip scalars          [N][F]
__device__ float g_sc1[3*NF];     // skip vectors SoA      [3][N][F]
__device__ float g_h3[Ee*64];     // radial MLP hidden     [E][64]
__device__ float g_a0[NF];        // scatter accum scalars [N][F]
__device__ float g_a1[3*NF];      // scatter accum vec SoA [3][N][F]

// species grouping (for k_up_g)
__device__ int g_off[Zz + 1];     // block-offset prefix (in 8-node blocks)
__device__ int g_list[LIST_CAP];

__device__ __forceinline__ float silu_f(float x) { return x / (1.0f + expf(-x)); }

__device__ __forceinline__ void red4(float* p, float a, float b, float c, float d) {
    asm volatile("red.global.add.v4.f32 [%0], {%1,%2,%3,%4};"
                 :: "l"(p), "f"(a), "f"(b), "f"(c), "f"(d) : "memory");
}

// ---------------- zero accumulators + grouping state --------------------------
__global__ void k_zero() {
    int stride = gridDim.x * blockDim.x;
    int tid = blockIdx.x * blockDim.x + threadIdx.x;
    float4 z4 = make_float4(0.f, 0.f, 0.f, 0.f);
    float4* a0 = reinterpret_cast<float4*>(g_a0);
    float4* a1 = reinterpret_cast<float4*>(g_a1);
    for (int i = tid; i < NF/4; i += stride) a0[i] = z4;
    for (int i = tid; i < 3*NF/4; i += stride) a1[i] = z4;
    for (int i = tid; i < LIST_CAP; i += stride) g_list[i] = -1;
}

// ---------------- species grouping: single-block count/scan/scatter -----------
__global__ __launch_bounds__(256) void k_group(const int* __restrict__ species) {
    __shared__ int scnt[Zz], scur[Zz];
    int t = threadIdx.x;
    if (t < Zz) scnt[t] = 0;
    __syncthreads();
    for (int n = t; n < Nn; n += 256) atomicAdd(&scnt[species[n]], 1);
    __syncthreads();
    if (t == 0) {
        int off = 0;
        for (int z = 0; z < Zz; z++) {
            g_off[z] = off;
            scur[z]  = off * 8;
            off += (scnt[z] + 7) >> 3;
        }
        g_off[Zz] = off;
    }
    __syncthreads();
    for (int n = t; n < Nn; n += 256) {
        int pos = atomicAdd(&scur[species[n]], 1);
        g_list[pos] = n;
    }
}

// ---------------- radial MLP layers 1..3 (2 threads per edge, smem hidden) ----
// block = 64 edges, 128 threads. Hidden vector in smem (not registers) so
// register count stays ~64 -> high occupancy, FFMA-issue-bound.
__global__ __launch_bounds__(128) void k_mlp(
    const float* __restrict__ radial,
    const float* __restrict__ w1, const float* __restrict__ w2,
    const float* __restrict__ w3)
{
    __shared__ float w1s[8*64];        //  2 KB
    __shared__ float wbuf[64*64];      // 16 KB (holds w2, then w3)
    __shared__ float hbuf[64][65];     // 16.25 KB (pad 65: conflict-free)

    int tid = threadIdx.x;
    int el  = tid & 63;                // edge within block
    int jb  = (tid >> 6) * 32;         // output half: 0 or 32
    int e   = blockIdx.x * 64 + el;

    // cooperative loads: w1 (512 floats), w2 (4096 floats)
    reinterpret_cast<float4*>(w1s)[tid] = reinterpret_cast<const float4*>(w1)[tid];
    #pragma unroll
    for (int i = 0; i < 8; i++)
        reinterpret_cast<float4*>(wbuf)[tid + i*128] =
            reinterpret_cast<const float4*>(w2)[tid + i*128];

    float4 r0 = *reinterpret_cast<const float4*>(&radial[e*8]);
    float4 r1 = *reinterpret_cast<const float4*>(&radial[e*8 + 4]);
    __syncthreads();

    // ---- layer 1: 8 -> 64 (this thread: 32 outputs) ----
    float acc[32];
    #pragma unroll
    for (int j = 0; j < 32; j++) {
        int c = jb + j;
        acc[j] = r0.x*w1s[0*64+c] + r0.y*w1s[1*64+c]
               + r0.z*w1s[2*64+c] + r0.w*w1s[3*64+c]
               + r1.x*w1s[4*64+c] + r1.y*w1s[5*64+c]
               + r1.z*w1s[6*64+c] + r1.w*w1s[7*64+c];
    }
    #pragma unroll
    for (int j = 0; j < 32; j++)
        hbuf[el][jb + j] = silu_f(acc[j] * INV_SQ8);
    __syncthreads();

    // ---- layer 2: 64 -> 64 ----
    #pragma unroll
    for (int j = 0; j < 32; j++) acc[j] = 0.f;
    #pragma unroll 4
    for (int k = 0; k < 64; k++) {
        float h = hbuf[el][k];
        const float4* wr = reinterpret_cast<const float4*>(&wbuf[k*64 + jb]);
        #pragma unroll
        for (int j4 = 0; j4 < 8; j4++) {
            float4 w = wr[j4];
            acc[j4*4+0] += h*w.x; acc[j4*4+1] += h*w.y;
            acc[j4*4+2] += h*w.z; acc[j4*4+3] += h*w.w;
        }
    }
    __syncthreads();   // all hbuf/wbuf(w2) reads complete
    #pragma unroll
    for (int j = 0; j < 32; j++)
        hbuf[el][jb + j] = silu_f(acc[j] * 0.125f);
    #pragma unroll
    for (int i = 0; i < 8; i++)
        reinterpret_cast<float4*>(wbuf)[tid + i*128] =
            reinterpret_cast<const float4*>(w3)[tid + i*128];
    __syncthreads();

    // ---- layer 3: 64 -> 64 ----
    #pragma unroll
    for (int j = 0; j < 32; j++) acc[j] = 0.f;
    #pragma unroll 4
    for (int k = 0; k < 64; k++) {
        float h = hbuf[el][k];
        const float4* wr = reinterpret_cast<const float4*>(&wbuf[k*64 + jb]);
        #pragma unroll
        for (int j4 = 0; j4 < 8; j4++) {
            float4 w = wr[j4];
            acc[j4*4+0] += h*w.x; acc[j4*4+1] += h*w.y;
            acc[j4*4+2] += h*w.z; acc[j4*4+3] += h*w.w;
        }
    }
    float* dst = &g_h3[e*64 + jb];
    #pragma unroll
    for (int j4 = 0; j4 < 8; j4++) {
        float4 o = make_float4(silu_f(acc[j4*4+0]*0.125f),
                               silu_f(acc[j4*4+1]*0.125f),
                               silu_f(acc[j4*4+2]*0.125f),
                               silu_f(acc[j4*4+3]*0.125f));
        *reinterpret_cast<float4*>(dst + j4*4) = o;
    }
}

// ---------------- linear_up + species skip, 8 same-species nodes per block ----
__global__ __launch_bounds__(128) void k_up_g(
    const float* __restrict__ nf0, const float* __restrict__ nf1,
    const float* __restrict__ wu0, const float* __restrict__ wu1,
    const float* __restrict__ wz0a, const float* __restrict__ wz1a)
{
    int b = blockIdx.x;
    if (b >= g_off[Zz]) return;
    int z = 0;
    #pragma unroll
    for (int t = 1; t <= Zz; t++) if (b >= g_off[t]) z = t;
    int g = threadIdx.x;
    __shared__ int nd[8];
    __shared__ float s0t[128][8], sxt[128][8], syt[128][8], szt[128][8];
    if (g < 8) nd[g] = g_list[b*8 + g];
    __syncthreads();
    #pragma unroll
    for (int i = 0; i < 8; i++) {
        int ni = nd[i];
        float a = 0.f, bx = 0.f, by = 0.f, bz = 0.f;
        if (ni >= 0) {
            a = nf0[ni*Ff + g];
            const float* p = &nf1[(ni*Ff + g)*3];
            bx = p[0]; by = p[1]; bz = p[2];
        }
        s0t[g][i] = a; sxt[g][i] = bx; syt[g][i] = by; szt[g][i] = bz;
    }
    __syncthreads();

    const float* wz0 = wz0a + z*16384;
    const float* wz1 = wz1a + z*16384;

    float x0[8] = {}, xx[8] = {}, xy[8] = {}, xz[8] = {};
    float c0[8] = {}, cx[8] = {}, cy[8] = {}, cz[8] = {};
    #pragma unroll 4
    for (int f = 0; f < 128; f++) {
        float u0 = wu0[f*128 + g];
        float u1 = wu1[f*128 + g];
        float z0 = wz0[f*128 + g];
        float z1 = wz1[f*128 + g];
        float av[8], bxv[8], byv[8], bzv[8];
        *reinterpret_cast<float4*>(&av[0])  = *reinterpret_cast<const float4*>(&s0t[f][0]);
        *reinterpret_cast<float4*>(&av[4])  = *reinterpret_cast<const float4*>(&s0t[f][4]);
        *reinterpret_cast<float4*>(&bxv[0]) = *reinterpret_cast<const float4*>(&sxt[f][0]);
        *reinterpret_cast<float4*>(&bxv[4]) = *reinterpret_cast<const float4*>(&sxt[f][4]);
        *reinterpret_cast<float4*>(&byv[0]) = *reinterpret_cast<const float4*>(&syt[f][0]);
        *reinterpret_cast<float4*>(&byv[4]) = *reinterpret_cast<const float4*>(&syt[f][4]);
        *reinterpret_cast<float4*>(&bzv[0]) = *reinterpret_cast<const float4*>(&szt[f][0]);
        *reinterpret_cast<float4*>(&bzv[4]) = *reinterpret_cast<const float4*>(&szt[f][4]);
        #pragma unroll
        for (int i = 0; i < 8; i++) {
            x0[i] += av[i]*u0;   c0[i] += av[i]*z0;
            xx[i] += bxv[i]*u1;  xy[i] += byv[i]*u1;  xz[i] += bzv[i]*u1;
            cx[i] += bxv[i]*z1;  cy[i] += byv[i]*z1;  cz[i] += bzv[i]*z1;
        }
    }
    #pragma unroll
    for (int i = 0; i < 8; i++) {
        int ni = nd[i];
        if (ni < 0) continue;
        int o = ni*Ff + g;
        g_x0[o]        = x0[i]*INV_SQF;
        g_x1[o]        = xx[i]*INV_SQF;
        g_x1[NF + o]   = xy[i]*INV_SQF;
        g_x1[2*NF + o] = xz[i]*INV_SQF;
        g_sc0[o]        = c0[i]*INV_SQFZ;
        g_sc1[o]        = cx[i]*INV_SQFZ;
        g_sc1[NF + o]   = cy[i]*INV_SQFZ;
        g_sc1[2*NF + o] = cz[i]*INV_SQFZ;
    }
}

// ---------------- fused mix-GEMM + tensor product + scatter -------------------
// block = 32 edges, 256 threads, 2 blocks/SM pinned. GEMM [32,64]@[64,640]
// in registers (acc[path][edge][8]); BK=8 staging; direct red4 scatter.
__global__ __launch_bounds__(256, 2) void k_mixtp(
    const float* __restrict__ vectors,
    const int*   __restrict__ senders,
    const int*   __restrict__ receivers,
    const float* __restrict__ w4)
{
    __shared__ float sh_h[32][64];     //  8192 B
    __shared__ float sh_w[8][640];     // 20480 B
    __shared__ float sh_Y[32][3];
    __shared__ int   sh_s[32], sh_r[32];

    int tid = threadIdx.x;
    int e0  = blockIdx.x * 32;

    if (tid < 32) {
        int e = e0 + tid;
        sh_s[tid] = senders[e];
        sh_r[tid] = receivers[e];
        float vx = vectors[e*3+0], vy = vectors[e*3+1], vz = vectors[e*3+2];
        float inv = SQ3c / (sqrtf(vx*vx + vy*vy + vz*vz) + 1e-12f);
        sh_Y[tid][0] = vx*inv; sh_Y[tid][1] = vy*inv; sh_Y[tid][2] = vz*inv;
    }
    for (int i = tid; i < 512; i += 256) {
        int row = i >> 4, c = i & 15;
        *reinterpret_cast<float4*>(&sh_h[row][c*4]) =
            *reinterpret_cast<const float4*>(&g_h3[(e0+row)*64 + c*4]);
    }

    int er  = (tid >> 4) * 2;
    int q   = tid & 15;
    int cg0 = q * 4;
    int cg1 = 64 + q * 4;

    float acc[5][2][8] = {};

    for (int kb = 0; kb < 64; kb += 8) {
        __syncthreads();
        for (int i = tid; i < 1280; i += 256) {
            int row = i / 160, c = i % 160;
            *reinterpret_cast<float4*>(&sh_w[row][c*4]) =
                *reinterpret_cast<const float4*>(&w4[(kb+row)*640 + c*4]);
        }
        __syncthreads();
        #pragma unroll
        for (int k = 0; k < 8; k++) {
            float a0 = sh_h[er][kb+k];
            float a1 = sh_h[er+1][kb+k];
            #pragma unroll
            for (int p = 0; p < 5; p++) {
                float4 b0 = *reinterpret_cast<const float4*>(&sh_w[k][p*128 + cg0]);
                float4 b1 = *reinterpret_cast<const float4*>(&sh_w[k][p*128 + cg1]);
                acc[p][0][0] += a0*b0.x; acc[p][0][1] += a0*b0.y;
                acc[p][0][2] += a0*b0.z; acc[p][0][3] += a0*b0.w;
                acc[p][0][4] += a0*b1.x; acc[p][0][5] += a0*b1.y;
                acc[p][0][6] += a0*b1.z; acc[p][0][7] += a0*b1.w;
                acc[p][1][0] += a1*b0.x; acc[p][1][1] += a1*b0.y;
                acc[p][1][2] += a1*b0.z; acc[p][1][3] += a1*b0.w;
                acc[p][1][4] += a1*b1.x; acc[p][1][5] += a1*b1.y;
                acc[p][1][6] += a1*b1.z; acc[p][1][7] += a1*b1.w;
            }
        }
    }

    #pragma unroll
    for (int ee = 0; ee < 2; ee++) {
        int el = er + ee;
        int s = sh_s[el], r = sh_r[el];
        float Yx = sh_Y[el][0], Yy = sh_Y[el][1], Yz = sh_Y[el][2];
        #pragma unroll
        for (int grp = 0; grp < 2; grp++) {
            int cg = grp ? cg1 : cg0;
            float m0a[4], mxa[4], mya[4], mza[4];
            *reinterpret_cast<float4*>(m0a) = *reinterpret_cast<const float4*>(&g_x0[s*Ff + cg]);
            *reinterpret_cast<float4*>(mxa) = *reinterpret_cast<const float4*>(&g_x1[s*Ff + cg]);
            *reinterpret_cast<float4*>(mya) = *reinterpret_cast<const float4*>(&g_x1[NF + s*Ff + cg]);
            *reinterpret_cast<float4*>(mza) = *reinterpret_cast<const float4*>(&g_x1[2*NF + s*Ff + cg]);
            float o0[4], ox[4], oy[4], oz[4];
            #pragma unroll
            for (int j = 0; j < 4; j++) {
                int jj = grp*4 + j;
                float w0 = acc[0][ee][jj], w1 = acc[1][ee][jj];
                float w2 = acc[2][ee][jj], w3 = acc[3][ee][jj];
                float w4c = acc[4][ee][jj];
                float M0 = m0a[j];
                float M1x = mxa[j], M1y = mya[j], M1z = mza[j];

                float dot = (M1x*Yx + M1y*Yy + M1z*Yz) * INV_SQ3;
                o0[j] = (w0*M0 + w1*dot) * TP_SCALE;

                float oux = M0*Yx*INV_SQ3, ouy = M0*Yy*INV_SQ3, ouz = M0*Yz*INV_SQ3;
                float crx = (M1y*Yz - M1z*Yy) * INV_SQ3;
                float cry = (M1z*Yx - M1x*Yz) * INV_SQ3;
                float crz = (M1x*Yy - M1y*Yx) * INV_SQ3;

                ox[j] = (w2*oux + w3*M1x + w4c*crx) * TP_SCALE;
                oy[j] = (w2*ouy + w3*M1y + w4c*cry) * TP_SCALE;
                oz[j] = (w2*ouz + w3*M1z + w4c*crz) * TP_SCALE;
            }
            red4(&g_a0[r*Ff + cg],        o0[0], o0[1], o0[2], o0[3]);
            red4(&g_a1[r*Ff + cg],        ox[0], ox[1], ox[2], ox[3]);
            red4(&g_a1[NF + r*Ff + cg],   oy[0], oy[1], oy[2], oy[3]);
            red4(&g_a1[2*NF + r*Ff + cg], oz[0], oz[1], oz[2], oz[3]);
        }
    }
}

// ---------------- down + symmetric contraction + post + readout ---------------
__global__ __launch_bounds__(128) void k_post_g(
    const int*   __restrict__ species,
    const float* __restrict__ wd0, const float* __restrict__ wd1,
    const float* __restrict__ wsc_all,
    const float* __restrict__ wp0, const float* __restrict__ wp1,
    const float* __restrict__ wr0,
    float* __restrict__ out_node, float* __restrict__ out_f0,
    float* __restrict__ out_f1)
{
    int g = threadIdx.x;
    int nb = blockIdx.x * 8;
    __shared__ float t0[128][8], tx[128][8], ty[128][8], tz[128][8];
    #pragma unroll
    for (int i = 0; i < 8; i++) {
        int o = (nb+i)*Ff + g;
        t0[g][i] = g_a0[o];
        tx[g][i] = g_a1[o];
        ty[g][i] = g_a1[NF + o];
        tz[g][i] = g_a1[2*NF + o];
    }
    __syncthreads();

    float s[8] = {}, v0[8] = {}, v1[8] = {}, v2[8] = {};
    #pragma unroll 4
    for (int f = 0; f < 128; f++) {
        float a = wd0[f*128 + g];
        float b = wd1[f*128 + g];
        float av[8], bxv[8], byv[8], bzv[8];
        *reinterpret_cast<float4*>(&av[0])  = *reinterpret_cast<const float4*>(&t0[f][0]);
        *reinterpret_cast<float4*>(&av[4])  = *reinterpret_cast<const float4*>(&t0[f][4]);
        *reinterpret_cast<float4*>(&bxv[0]) = *reinterpret_cast<const float4*>(&tx[f][0]);
        *reinterpret_cast<float4*>(&bxv[4]) = *reinterpret_cast<const float4*>(&tx[f][4]);
        *reinterpret_cast<float4*>(&byv[0]) = *reinterpret_cast<const float4*>(&ty[f][0]);
        *reinterpret_cast<float4*>(&byv[4]) = *reinterpret_cast<const float4*>(&ty[f][4]);
        *reinterpret_cast<float4*>(&bzv[0]) = *reinterpret_cast<const float4*>(&tz[f][0]);
        *reinterpret_cast<float4*>(&bzv[4]) = *reinterpret_cast<const float4*>(&tz[f][4]);
        #pragma unroll
        for (int i = 0; i < 8; i++) {
            s[i]  += av[i]*a;
            v0[i] += bxv[i]*b; v1[i] += byv[i]*b; v2[i] += bzv[i]*b;
        }
    }

    float b0[8], cc[8];
    #pragma unroll
    for (int i = 0; i < 8; i++) {
        float ss = s[i]*INV_SQF;
        float wx = v0[i]*INV_SQF, wy = v1[i]*INV_SQF, wz = v2[i]*INV_SQF;
        v0[i] = wx; v1[i] = wy; v2[i] = wz;
        float vv = wx*wx + wy*wy + wz*wz;
        float s2 = ss*ss;
        int sp = species[nb+i];
        const float* w = wsc_all + sp*1152;
        b0[i] = (w[g]*ss + w[128+g]*s2 + w[256+g]*vv
               + w[384+g]*s2*ss + w[512+g]*ss*vv) * INV_SQZ;
        cc[i] = (w[640+g] + w[768+g]*ss + w[896+g]*s2
               + w[1024+g]*vv) * INV_SQZ;
    }
    __syncthreads();
    #pragma unroll
    for (int i = 0; i < 8; i++) {
        t0[g][i] = b0[i];
        tx[g][i] = cc[i]*v0[i];
        ty[g][i] = cc[i]*v1[i];
        tz[g][i] = cc[i]*v2[i];
    }
    __syncthreads();

    float f0[8] = {}, f1x[8] = {}, f1y[8] = {}, f1z[8] = {};
    #pragma unroll 4
    for (int f = 0; f < 128; f++) {
        float a = wp0[f*128 + g];
        float b = wp1[f*128 + g];
        float av[8], bxv[8], byv[8], bzv[8];
        *reinterpret_cast<float4*>(&av[0])  = *reinterpret_cast<const float4*>(&t0[f][0]);
        *reinterpret_cast<float4*>(&av[4])  = *reinterpret_cast<const float4*>(&t0[f][4]);
        *reinterpret_cast<float4*>(&bxv[0]) = *reinterpret_cast<const float4*>(&tx[f][0]);
        *reinterpret_cast<float4*>(&bxv[4]) = *reinterpret_cast<const float4*>(&tx[f][4]);
        *reinterpret_cast<float4*>(&byv[0]) = *reinterpret_cast<const float4*>(&ty[f][0]);
        *reinterpret_cast<float4*>(&byv[4]) = *reinterpret_cast<const float4*>(&ty[f][4]);
        *reinterpret_cast<float4*>(&bzv[0]) = *reinterpret_cast<const float4*>(&tz[f][0]);
        *reinterpret_cast<float4*>(&bzv[4]) = *reinterpret_cast<const float4*>(&tz[f][4]);
        #pragma unroll
        for (int i = 0; i < 8; i++) {
            f0[i]  += av[i]*a;
            f1x[i] += bxv[i]*b; f1y[i] += byv[i]*b; f1z[i] += bzv[i]*b;
        }
    }

    float wr = wr0[g];
    float cr[8];
    #pragma unroll
    for (int i = 0; i < 8; i++) {
        int o = (nb+i)*Ff + g;
        float F0 = f0[i]*INV_SQF  + g_sc0[o];
        float X  = f1x[i]*INV_SQF + g_sc1[o];
        float Y  = f1y[i]*INV_SQF + g_sc1[NF + o];
        float Zv = f1z[i]*INV_SQF + g_sc1[2*NF + o];
        out_f0[o] = F0;
        float* po = &out_f1[o*3];
        po[0] = X; po[1] = Y; po[2] = Zv;
        cr[i] = F0 * wr;
    }
    #pragma unroll
    for (int off = 16; off; off >>= 1)
        #pragma unroll
        for (int i = 0; i < 8; i++)
            cr[i] += __shfl_down_sync(0xffffffffu, cr[i], off);
    __shared__ float sred[4][8];
    int lane = g & 31, wrp = g >> 5;
    if (lane == 0)
        #pragma unroll
        for (int i = 0; i < 8; i++) sred[wrp][i] = cr[i];
    __syncthreads();
    if (g < 8)
        out_node[nb+g] = (sred[0][g] + sred[1][g] + sred[2][g] + sred[3][g]) * INV_SQF;
}

// ---------------- launch ------------------------------------------------------
extern "C" void kernel_launch(void* const* d_in, const int* in_sizes, int n_in,
                              void* d_out, int out_size)
{
    const float* vectors   = (const float*)d_in[0];
    const float* nf0       = (const float*)d_in[1];
    const float* nf1       = (const float*)d_in[2];
    const float* radial    = (const float*)d_in[3];
    const int*   species   = (const int*)  d_in[4];
    const int*   senders   = (const int*)  d_in[5];
    const int*   receivers = (const int*)  d_in[6];
    const float* wz0       = (const float*)d_in[7];
    const float* wz1       = (const float*)d_in[8];
    const float* wu0       = (const float*)d_in[9];
    const float* wu1       = (const float*)d_in[10];
    const float* mw1       = (const float*)d_in[11];
    const float* mw2       = (const float*)d_in[12];
    const float* mw3       = (const float*)d_in[13];
    const float* mw4       = (const float*)d_in[14];
    const float* wd0       = (const float*)d_in[15];
    const float* wd1       = (const float*)d_in[16];
    const float* wsc       = (const float*)d_in[17];
    const float* wp0       = (const float*)d_in[18];
    const float* wp1       = (const float*)d_in[19];
    const float* wr0       = (const float*)d_in[20];

    float* out      = (float*)d_out;
    float* out_node = out;                 // [N]
    float* out_f0   = out + Nn;            // [N,F]
    float* out_f1   = out + Nn + NF;       // [N,F,3]

    // slot 4 (k_up_g) gets profiled by ncu
    k_zero  <<<512, 256>>>();
    k_group <<<1, 256>>>(species);
    k_mlp   <<<Ee/64, 128>>>(radial, mw1, mw2, mw3);
    k_up_g  <<<NBLK_UP, 128>>>(nf0, nf1, wu0, wu1, wz0, wz1);
    k_mixtp <<<Ee/32, 256>>>(vectors, senders, receivers, mw4);
    k_post_g<<<Nn/8, 128>>>(species, wd0, wd1, wsc, wp0, wp1, wr0,
                            out_node, out_f0, out_f1);
}